// round 13
// baseline (speedup 1.0000x reference)
#include <cuda_runtime.h>
#include <cstdint>
#include <climits>

// ---------------- problem constants (match reference exactly) ----------------
#define BB   4
#define NPTS 300000
#define NC   5
#define GXX  432
#define GYY  496
#define GZZ  1
#define NVOX (GXX * GYY * GZZ)          // 214272 (divisible by 4)
#define MAXV 40000
#define MAXP 30
#define CAP  48                          // per-voxel index bucket capacity
#define CHUNK 4096
#define NB   ((NVOX + CHUNK - 1) / CHUNK)   // 53

#define FEATS_ELEMS ((size_t)BB * MAXV * MAXP * NC)   // 24,000,000 floats

#define I4_CNT   ((BB * NVOX) / 4)
#define I4_AGG   ((BB * NB + 3) / 4)
#define I4_VL    ((BB * MAXV) / 4)
#define FILL_TOTAL (I4_CNT + I4_AGG + I4_VL)

#define VALIDF (1 << 30)
#define ROWF   (MAXP * NC)               // 150 floats per feats row
#define RPB    32                         // rows per k_out block
#define NBLK_OUT ((BB * MAXV) / RPB)      // 5000

// ---------------- static device scratch (16B-aligned for vector ops) ----------
__device__ int4 g_count4[(BB * NVOX) / 4];
__device__ int4 g_agg4  [I4_AGG];
__device__ int4 g_vlist4[I4_VL];         // row -> vid (or -1)
__device__ int  g_bucket[(size_t)BB * NVOX * CAP];

#define G_COUNT ((int*)g_count4)
#define G_AGG   ((int*)g_agg4)
#define G_VLIST ((int*)g_vlist4)

// ---------------- init: counts=0, agg=0, vlist=-1 ------------------------------
__global__ void k_fill() {
    int i = blockIdx.x * blockDim.x + threadIdx.x;
    if (i < I4_CNT) { g_count4[i] = make_int4(0, 0, 0, 0); return; }
    i -= I4_CNT;
    if (i < I4_AGG) { g_agg4[i] = make_int4(0, 0, 0, 0); return; }
    i -= I4_AGG;
    if (i < I4_VL)  { g_vlist4[i] = make_int4(-1, -1, -1, -1); }
}

// ---------------- pass 1: voxelize + bucket append ----------------------------
__global__ void k_points(const float* __restrict__ pts) {
    int tid = blockIdx.x * blockDim.x + threadIdx.x;
    if (tid >= BB * NPTS) return;
    int b = tid / NPTS;
    int n = tid - b * NPTS;
    const float* p = pts + (size_t)tid * NC;
    float x = __ldg(p + 0), y = __ldg(p + 1), z = __ldg(p + 2);
    // identical float32 ops as reference: floor((p - lo) / vs)
    int ix = (int)floorf((x - 0.0f)   / 0.16f);
    int iy = (int)floorf((y + 39.68f) / 0.16f);
    int iz = (int)floorf((z + 3.0f)   / 4.0f);
    if (ix < 0 || ix >= GXX || iy < 0 || iy >= GYY || iz < 0 || iz >= GZZ) return;
    int vid = (iz * GYY + iy) * GXX + ix;
    int cell = b * NVOX + vid;
    int pos = atomicAdd(&G_COUNT[cell], 1);
    if (pos < CAP) g_bucket[(size_t)cell * CAP + pos] = n;
}

// ---------------- single-pass scan with decoupled lookback --------------------
// 212 blocks (256 thr, 16 cells/thread) fit in one wave -> spin-wait is safe.
// Output: vlist[b*MAXV + rank] = vid for the first MAXV occupied voxels.
__global__ void k_scan() {
    int blk = blockIdx.x;
    int b  = blk / NB;
    int cb = blk - b * NB;
    int t  = threadIdx.x;
    __shared__ int sh[256];

    int base = cb * CHUNK + t * 16;
    int f[16];
    int s = 0;
    #pragma unroll
    for (int q = 0; q < 16; q += 4) {
        if (base + q < NVOX) {
            int4 c4 = __ldg((const int4*)(G_COUNT + b * NVOX + base + q));
            f[q + 0] = (c4.x > 0);
            f[q + 1] = (c4.y > 0);
            f[q + 2] = (c4.z > 0);
            f[q + 3] = (c4.w > 0);
        } else {
            f[q + 0] = f[q + 1] = f[q + 2] = f[q + 3] = 0;
        }
        s += f[q + 0] + f[q + 1] + f[q + 2] + f[q + 3];
    }
    sh[t] = s;
    __syncthreads();
    #pragma unroll
    for (int off = 1; off < 256; off <<= 1) {   // Hillis–Steele inclusive
        int v = (t >= off) ? sh[t - off] : 0;
        __syncthreads();
        sh[t] += v;
        __syncthreads();
    }
    int excl  = sh[t] - s;
    int total = sh[255];

    if (t == 0) atomicExch(&G_AGG[blk], total | VALIDF);

    int partial = 0;
    for (int j = t; j < cb; j += 256) {
        int v;
        do { v = atomicAdd(&G_AGG[b * NB + j], 0); } while (!(v & VALIDF));
        partial += (v & (VALIDF - 1));
    }
    __syncthreads();
    sh[t] = partial;
    __syncthreads();
    #pragma unroll
    for (int off = 128; off > 0; off >>= 1) {
        if (t < off) sh[t] += sh[t + off];
        __syncthreads();
    }
    int r = sh[0] + excl;

    int* vl = G_VLIST + b * MAXV;
    #pragma unroll
    for (int q = 0; q < 16; q++) {
        if (f[q]) {
            if (r < MAXV) vl[r] = base + q;
            r++;
        }
    }
}

// ---------------- fused output, software-pipelined ------------------------------
// Block owns 32 rows. 8 threads/row. The full gather (cnt -> bucket -> rank ->
// point floats) runs BEFORE the barrier, hidden under the tile's zero stores;
// after the barrier only register->gmem stores remain.
__global__ __launch_bounds__(256) void k_out(const float* __restrict__ pts,
                                             float* __restrict__ out) {
    int r0   = blockIdx.x * RPB;
    int t    = threadIdx.x;
    int row  = r0 + (t >> 3);             // 8 threads per row
    int sub  = t & 7;
    int b    = row / MAXV;

    // head of the dependent chain — issue immediately
    int vid = __ldg(&G_VLIST[row]);

    // phase 1a: start streaming zeros (independent of everything)
    float4* o4 = (float4*)(out + (size_t)r0 * ROWF);
    const float4 z4 = make_float4(0.f, 0.f, 0.f, 0.f);
    #pragma unroll
    for (int i = t; i < RPB * ROWF / 4; i += 256) o4[i] = z4;

    // phase 1b: gather into registers while zero stores drain.
    // Thread sub owns bucket entries sub and sub+8 (covers m <= 16; avg m~1.9).
    int cell = 0, m = 0;
    const int* bk = nullptr;
    int   e[2]  = { -1, -1 };
    int   rk[2] = { 0, 0 };
    float ft[2][NC];
    if (vid >= 0) {
        cell = b * NVOX + vid;
        int cnt = __ldg(&G_COUNT[cell]);  // same addr for 8 threads -> broadcast
        m = cnt < CAP ? cnt : CAP;
        bk = g_bucket + (size_t)cell * CAP;
        #pragma unroll
        for (int u = 0; u < 2; u++) {
            int j = sub + u * 8;
            if (j < m) e[u] = __ldg(bk + j);
        }
        #pragma unroll
        for (int u = 0; u < 2; u++) {
            if (e[u] >= 0) {
                int r = 0;                 // original-order rank (L1-hot line)
                for (int q = 0; q < m; q++) r += (__ldg(bk + q) < e[u]);
                rk[u] = r;
                if (r < MAXP) {
                    const float* p = pts + ((size_t)b * NPTS + e[u]) * NC;
                    ft[u][0] = (__ldg(p + 0) - 0.0f)   / 69.12f;
                    ft[u][1] = (__ldg(p + 1) + 39.68f) / 79.36f;
                    ft[u][2] = (__ldg(p + 2) + 3.0f)   / 4.0f;
                    ft[u][3] = __ldg(p + 3);
                    ft[u][4] = __ldg(p + 4);
                }
            }
        }
    }

    // coords row (disjoint from feats tile, no ordering needed)
    if (sub == 0) {
        float4* co = (float4*)(out + FEATS_ELEMS) + row;
        if (vid >= 0) {
            int izc = vid / (GXX * GYY);
            int rem = vid - izc * (GXX * GYY);
            *co = make_float4((float)b, (float)izc,
                              (float)(rem / GXX), (float)(rem % GXX));
        } else {
            *co = make_float4(-1.f, -1.f, -1.f, -1.f);
        }
    }

    // zeros must land before overwrites to the same tile
    __syncthreads();

    // phase 2: pure stores from registers
    #pragma unroll
    for (int u = 0; u < 2; u++) {
        if (e[u] >= 0 && rk[u] < MAXP) {
            float* fo = out + (size_t)row * ROWF + rk[u] * NC;
            fo[0] = ft[u][0];
            fo[1] = ft[u][1];
            fo[2] = ft[u][2];
            fo[3] = ft[u][3];
            fo[4] = ft[u][4];
        }
    }
    // rare slow path: bucket entries beyond 16 (P ~ 0 for lambda=1.4)
    for (int j = sub + 16; j < m; j += 8) {
        int ee = __ldg(bk + j);
        int r = 0;
        for (int q = 0; q < m; q++) r += (__ldg(bk + q) < ee);
        if (r >= MAXP) continue;
        const float* p = pts + ((size_t)b * NPTS + ee) * NC;
        float* fo = out + (size_t)row * ROWF + r * NC;
        fo[0] = (__ldg(p + 0) - 0.0f)   / 69.12f;
        fo[1] = (__ldg(p + 1) + 39.68f) / 79.36f;
        fo[2] = (__ldg(p + 2) + 3.0f)   / 4.0f;
        fo[3] = __ldg(p + 3);
        fo[4] = __ldg(p + 4);
    }
}

// ---------------- launch ------------------------------------------------------
extern "C" void kernel_launch(void* const* d_in, const int* in_sizes, int n_in,
                              void* d_out, int out_size) {
    const float* pts = (const float*)d_in[0];
    float* out = (float*)d_out;

    k_fill  <<<(FILL_TOTAL + 255) / 256, 256>>>();
    k_points<<<(BB * NPTS + 255) / 256, 256>>>(pts);
    k_scan  <<<BB * NB, 256>>>();
    k_out   <<<NBLK_OUT, 256>>>(pts, out);
}

// round 14
// speedup vs baseline: 1.0473x; 1.0473x over previous
#include <cuda_runtime.h>
#include <cstdint>
#include <climits>

// ---------------- problem constants (match reference exactly) ----------------
#define BB   4
#define NPTS 300000
#define NC   5
#define GXX  432
#define GYY  496
#define GZZ  1
#define NVOX (GXX * GYY * GZZ)          // 214272 (divisible by 4)
#define MAXV 40000
#define MAXP 30
#define CAP  48                          // per-voxel index bucket capacity
#define CHUNK 4096
#define NB   ((NVOX + CHUNK - 1) / CHUNK)   // 53

#define FEATS_ELEMS ((size_t)BB * MAXV * MAXP * NC)   // 24,000,000 floats

#define I4_CNT   ((BB * NVOX) / 4)
#define I4_AGG   ((BB * NB + 3) / 4)
#define I4_VL    ((BB * MAXV) / 4)
#define FILL_TOTAL (I4_CNT + I4_AGG + I4_VL)

#define VALIDF (1 << 30)
#define ROWF   (MAXP * NC)               // 150 floats per feats row
#define RPB    32                         // rows per k_out block
#define NBLK_OUT ((BB * MAXV) / RPB)      // 5000

// ---------------- static device scratch (16B-aligned for vector ops) ----------
__device__ int4 g_count4[(BB * NVOX) / 4];
__device__ int4 g_agg4  [I4_AGG];
__device__ int4 g_vlist4[I4_VL];         // row -> vid (or -1)
__device__ int  g_bucket[(size_t)BB * NVOX * CAP];

#define G_COUNT ((int*)g_count4)
#define G_AGG   ((int*)g_agg4)
#define G_VLIST ((int*)g_vlist4)

// ---------------- init: counts=0, agg=0, vlist=-1 ------------------------------
__global__ void k_fill() {
    int i = blockIdx.x * blockDim.x + threadIdx.x;
    if (i < I4_CNT) { g_count4[i] = make_int4(0, 0, 0, 0); return; }
    i -= I4_CNT;
    if (i < I4_AGG) { g_agg4[i] = make_int4(0, 0, 0, 0); return; }
    i -= I4_AGG;
    if (i < I4_VL)  { g_vlist4[i] = make_int4(-1, -1, -1, -1); }
}

// ---------------- pass 1: voxelize + bucket append ----------------------------
__global__ void k_points(const float* __restrict__ pts) {
    int tid = blockIdx.x * blockDim.x + threadIdx.x;
    if (tid >= BB * NPTS) return;
    int b = tid / NPTS;
    int n = tid - b * NPTS;
    const float* p = pts + (size_t)tid * NC;
    float x = __ldg(p + 0), y = __ldg(p + 1), z = __ldg(p + 2);
    // identical float32 ops as reference: floor((p - lo) / vs)
    int ix = (int)floorf((x - 0.0f)   / 0.16f);
    int iy = (int)floorf((y + 39.68f) / 0.16f);
    int iz = (int)floorf((z + 3.0f)   / 4.0f);
    if (ix < 0 || ix >= GXX || iy < 0 || iy >= GYY || iz < 0 || iz >= GZZ) return;
    int vid = (iz * GYY + iy) * GXX + ix;
    int cell = b * NVOX + vid;
    int pos = atomicAdd(&G_COUNT[cell], 1);
    if (pos < CAP) g_bucket[(size_t)cell * CAP + pos] = n;
}

// ---------------- single-pass scan, warp-shuffle version ------------------------
// 212 blocks (256 thr, 16 cells/thread) fit in one wave -> spin-wait is safe.
// 4 block barriers total (was ~24). Aggregate published right after the 8-warp
// sum scan. Output: vlist[b*MAXV + rank] = vid for first MAXV occupied voxels.
__global__ void k_scan() {
    int blk  = blockIdx.x;
    int b    = blk / NB;
    int cb   = blk - b * NB;
    int t    = threadIdx.x;
    int lane = t & 31;
    int w    = t >> 5;                    // 8 warps
    __shared__ int warp_s[8];
    __shared__ int s_off;

    int base = cb * CHUNK + t * 16;
    int f[16];
    int s = 0;
    #pragma unroll
    for (int q = 0; q < 16; q += 4) {
        if (base + q < NVOX) {
            int4 c4 = __ldg((const int4*)(G_COUNT + b * NVOX + base + q));
            f[q + 0] = (c4.x > 0);
            f[q + 1] = (c4.y > 0);
            f[q + 2] = (c4.z > 0);
            f[q + 3] = (c4.w > 0);
        } else {
            f[q + 0] = f[q + 1] = f[q + 2] = f[q + 3] = 0;
        }
        s += f[q + 0] + f[q + 1] + f[q + 2] + f[q + 3];
    }

    // intra-warp inclusive scan of s
    int incl = s;
    #pragma unroll
    for (int off = 1; off < 32; off <<= 1) {
        int v = __shfl_up_sync(0xffffffffu, incl, off);
        if (lane >= off) incl += v;
    }
    if (lane == 31) warp_s[w] = incl;
    __syncthreads();                      // (1)

    // warp 0 scans the 8 warp sums; publishes the chunk aggregate immediately
    if (w == 0) {
        int ws = (lane < 8) ? warp_s[lane] : 0;
        int wincl = ws;
        #pragma unroll
        for (int off = 1; off < 8; off <<= 1) {
            int v = __shfl_up_sync(0xffffffffu, wincl, off);
            if (lane >= off) wincl += v;
        }
        if (lane < 8) warp_s[lane] = wincl - ws;     // exclusive warp offset
        if (lane == 7) atomicExch(&G_AGG[blk], wincl | VALIDF);  // total
    }
    __syncthreads();                      // (2)
    int excl = (incl - s) + warp_s[w];    // exclusive prefix within chunk

    // lookback: sum all predecessor aggregates (<= 52)
    int partial = 0;
    for (int j = t; j < cb; j += 256) {
        int v;
        do { v = atomicAdd(&G_AGG[b * NB + j], 0); } while (!(v & VALIDF));
        partial += (v & (VALIDF - 1));
    }
    #pragma unroll
    for (int off = 16; off > 0; off >>= 1)
        partial += __shfl_down_sync(0xffffffffu, partial, off);
    __syncthreads();                      // (3) warp_s reads (excl) done
    if (lane == 0) warp_s[w] = partial;
    __syncthreads();                      // (4)
    if (t == 0) {
        int tot = 0;
        #pragma unroll
        for (int q = 0; q < 8; q++) tot += warp_s[q];
        s_off = tot;
    }
    __syncthreads();                      // (5)
    int r = s_off + excl;

    int* vl = G_VLIST + b * MAXV;
    #pragma unroll
    for (int q = 0; q < 16; q++) {
        if (f[q]) {
            if (r < MAXV) vl[r] = base + q;
            r++;
        }
    }
}

// ---------------- fused output (R12 champion shape, verbatim) -------------------
// Block owns 32 rows (19200B feats + 32 coords). 8 threads per row keep all 32
// dependent gather chains in flight concurrently.
__global__ __launch_bounds__(256) void k_out(const float* __restrict__ pts,
                                             float* __restrict__ out) {
    int r0   = blockIdx.x * RPB;
    int t    = threadIdx.x;
    int row  = r0 + (t >> 3);             // 8 threads per row
    int sub  = t & 7;
    int b    = row / MAXV;

    // issue the row's vid load first; the zero loop hides its latency
    int vid = __ldg(&G_VLIST[row]);

    // phase 1: streaming-zero this block's feats tile directly in gmem
    float4* o4 = (float4*)(out + (size_t)r0 * ROWF);
    const float4 z4 = make_float4(0.f, 0.f, 0.f, 0.f);
    #pragma unroll
    for (int i = t; i < RPB * ROWF / 4; i += 256) o4[i] = z4;

    // coords row (disjoint from feats tile, no ordering needed)
    if (sub == 0) {
        float4* co = (float4*)(out + FEATS_ELEMS) + row;
        if (vid >= 0) {
            int izc = vid / (GXX * GYY);
            int rem = vid - izc * (GXX * GYY);
            *co = make_float4((float)b, (float)izc,
                              (float)(rem / GXX), (float)(rem % GXX));
        } else {
            *co = make_float4(-1.f, -1.f, -1.f, -1.f);
        }
    }

    // zeros must land before overwrites to the same tile
    __syncthreads();

    // phase 2: overwrite real points (avg ~1.9 per row)
    if (vid < 0) return;
    int cell = b * NVOX + vid;
    int cnt  = __ldg(&G_COUNT[cell]);
    int m    = cnt < CAP ? cnt : CAP;
    const int* bk = g_bucket + (size_t)cell * CAP;

    for (int j = sub; j < m; j += 8) {
        int e = __ldg(bk + j);
        // original-order rank: #(entries < e) — bucket line is L1-hot
        int rk = 0;
        for (int q = 0; q < m; q++) rk += (__ldg(bk + q) < e);
        if (rk >= MAXP) continue;
        const float* p = pts + ((size_t)b * NPTS + e) * NC;
        float* fo = out + (size_t)row * ROWF + rk * NC;
        fo[0] = (__ldg(p + 0) - 0.0f)   / 69.12f;
        fo[1] = (__ldg(p + 1) + 39.68f) / 79.36f;
        fo[2] = (__ldg(p + 2) + 3.0f)   / 4.0f;
        fo[3] = __ldg(p + 3);
        fo[4] = __ldg(p + 4);
    }
}

// ---------------- launch ------------------------------------------------------
extern "C" void kernel_launch(void* const* d_in, const int* in_sizes, int n_in,
                              void* d_out, int out_size) {
    const float* pts = (const float*)d_in[0];
    float* out = (float*)d_out;

    k_fill  <<<(FILL_TOTAL + 255) / 256, 256>>>();
    k_points<<<(BB * NPTS + 255) / 256, 256>>>(pts);
    k_scan  <<<BB * NB, 256>>>();
    k_out   <<<NBLK_OUT, 256>>>(pts, out);
}

// round 15
// speedup vs baseline: 1.0741x; 1.0256x over previous
#include <cuda_runtime.h>
#include <cstdint>
#include <climits>

// ---------------- problem constants (match reference exactly) ----------------
#define BB   4
#define NPTS 300000
#define NC   5
#define GXX  432
#define GYY  496
#define GZZ  1
#define NVOX (GXX * GYY * GZZ)          // 214272 (divisible by 4)
#define MAXV 40000
#define MAXP 30
#define CAP  48                          // per-voxel index bucket capacity
#define CHUNK 4096
#define NB   ((NVOX + CHUNK - 1) / CHUNK)   // 53

#define FEATS_ELEMS ((size_t)BB * MAXV * MAXP * NC)   // 24,000,000 floats

#define I4_CNT   ((BB * NVOX) / 4)
#define I4_AGG   ((BB * NB + 3) / 4)
#define I4_VL    ((BB * MAXV) / 4)
#define FILL_TOTAL (I4_CNT + I4_AGG + I4_VL)

#define VALIDF (1 << 30)
#define ROWF   (MAXP * NC)               // 150 floats per feats row
#define RPB    32                         // rows per k_out block
#define NBLK_OUT ((BB * MAXV) / RPB)      // 5000

// ---------------- static device scratch (16B-aligned for vector ops) ----------
__device__ int4 g_count4[(BB * NVOX) / 4];
__device__ int4 g_agg4  [I4_AGG];
__device__ int4 g_vlist4[I4_VL];         // row -> vid (or -1)
__device__ int  g_bucket[(size_t)BB * NVOX * CAP];

#define G_COUNT ((int*)g_count4)
#define G_AGG   ((int*)g_agg4)
#define G_VLIST ((int*)g_vlist4)

// ---------------- init: counts=0, agg=0, vlist=-1 ------------------------------
__global__ void k_fill() {
    int i = blockIdx.x * blockDim.x + threadIdx.x;
    if (i < I4_CNT) { g_count4[i] = make_int4(0, 0, 0, 0); return; }
    i -= I4_CNT;
    if (i < I4_AGG) { g_agg4[i] = make_int4(0, 0, 0, 0); return; }
    i -= I4_AGG;
    if (i < I4_VL)  { g_vlist4[i] = make_int4(-1, -1, -1, -1); }
}

// ---------------- pass 1: voxelize + bucket append ----------------------------
__global__ void k_points(const float* __restrict__ pts) {
    int tid = blockIdx.x * blockDim.x + threadIdx.x;
    if (tid >= BB * NPTS) return;
    int b = tid / NPTS;
    int n = tid - b * NPTS;
    const float* p = pts + (size_t)tid * NC;
    float x = __ldg(p + 0), y = __ldg(p + 1), z = __ldg(p + 2);
    // identical float32 ops as reference: floor((p - lo) / vs)
    int ix = (int)floorf((x - 0.0f)   / 0.16f);
    int iy = (int)floorf((y + 39.68f) / 0.16f);
    int iz = (int)floorf((z + 3.0f)   / 4.0f);
    if (ix < 0 || ix >= GXX || iy < 0 || iy >= GYY || iz < 0 || iz >= GZZ) return;
    int vid = (iz * GYY + iy) * GXX + ix;
    int cell = b * NVOX + vid;
    int pos = atomicAdd(&G_COUNT[cell], 1);
    if (pos < CAP) g_bucket[(size_t)cell * CAP + pos] = n;
}

// ---------------- single-pass scan, warp-shuffle version ------------------------
// 212 blocks (256 thr, 16 cells/thread) fit in one wave -> spin-wait is safe.
__global__ void k_scan() {
    int blk  = blockIdx.x;
    int b    = blk / NB;
    int cb   = blk - b * NB;
    int t    = threadIdx.x;
    int lane = t & 31;
    int w    = t >> 5;                    // 8 warps
    __shared__ int warp_s[8];
    __shared__ int s_off;

    int base = cb * CHUNK + t * 16;
    int f[16];
    int s = 0;
    #pragma unroll
    for (int q = 0; q < 16; q += 4) {
        if (base + q < NVOX) {
            int4 c4 = __ldg((const int4*)(G_COUNT + b * NVOX + base + q));
            f[q + 0] = (c4.x > 0);
            f[q + 1] = (c4.y > 0);
            f[q + 2] = (c4.z > 0);
            f[q + 3] = (c4.w > 0);
        } else {
            f[q + 0] = f[q + 1] = f[q + 2] = f[q + 3] = 0;
        }
        s += f[q + 0] + f[q + 1] + f[q + 2] + f[q + 3];
    }

    int incl = s;
    #pragma unroll
    for (int off = 1; off < 32; off <<= 1) {
        int v = __shfl_up_sync(0xffffffffu, incl, off);
        if (lane >= off) incl += v;
    }
    if (lane == 31) warp_s[w] = incl;
    __syncthreads();

    if (w == 0) {
        int ws = (lane < 8) ? warp_s[lane] : 0;
        int wincl = ws;
        #pragma unroll
        for (int off = 1; off < 8; off <<= 1) {
            int v = __shfl_up_sync(0xffffffffu, wincl, off);
            if (lane >= off) wincl += v;
        }
        if (lane < 8) warp_s[lane] = wincl - ws;     // exclusive warp offset
        if (lane == 7) atomicExch(&G_AGG[blk], wincl | VALIDF);  // total
    }
    __syncthreads();
    int excl = (incl - s) + warp_s[w];

    int partial = 0;
    for (int j = t; j < cb; j += 256) {
        int v;
        do { v = atomicAdd(&G_AGG[b * NB + j], 0); } while (!(v & VALIDF));
        partial += (v & (VALIDF - 1));
    }
    #pragma unroll
    for (int off = 16; off > 0; off >>= 1)
        partial += __shfl_down_sync(0xffffffffu, partial, off);
    __syncthreads();
    if (lane == 0) warp_s[w] = partial;
    __syncthreads();
    if (t == 0) {
        int tot = 0;
        #pragma unroll
        for (int q = 0; q < 8; q++) tot += warp_s[q];
        s_off = tot;
    }
    __syncthreads();
    int r = s_off + excl;

    int* vl = G_VLIST + b * MAXV;
    #pragma unroll
    for (int q = 0; q < 16; q++) {
        if (f[q]) {
            if (r < MAXV) vl[r] = base + q;
            r++;
        }
    }
}

// ---------------- fused output with light prefetch ------------------------------
// Block owns 32 rows. 8 threads/row. Pre-barrier we hoist only the cheap head
// of the gather chain (cnt + 2 speculative bucket entries, ~3 regs); the rank
// count, point loads, and stores stay post-barrier (chain depth 3 -> 1).
__global__ __launch_bounds__(256) void k_out(const float* __restrict__ pts,
                                             float* __restrict__ out) {
    int r0   = blockIdx.x * RPB;
    int t    = threadIdx.x;
    int row  = r0 + (t >> 3);             // 8 threads per row
    int sub  = t & 7;
    int b    = row / MAXV;

    // head of the dependent chain — issue immediately
    int vid = __ldg(&G_VLIST[row]);

    // phase 1: streaming-zero this block's feats tile directly in gmem
    float4* o4 = (float4*)(out + (size_t)r0 * ROWF);
    const float4 z4 = make_float4(0.f, 0.f, 0.f, 0.f);
    #pragma unroll
    for (int i = t; i < RPB * ROWF / 4; i += 256) o4[i] = z4;

    // prefetch: cnt + two speculative bucket entries (static array — entries
    // beyond cnt are stale but safely readable; discarded by the j<m guard)
    int cell = 0, cnt = 0, p0 = -1, p1 = -1;
    const int* bk = nullptr;
    if (vid >= 0) {
        cell = b * NVOX + vid;
        cnt  = __ldg(&G_COUNT[cell]);     // same addr for 8 threads -> broadcast
        bk   = g_bucket + (size_t)cell * CAP;
        p0   = __ldg(bk + sub);           // also warms the bucket line in L1
        p1   = __ldg(bk + sub + 8);
    }

    // coords row (disjoint from feats tile, no ordering needed)
    if (sub == 0) {
        float4* co = (float4*)(out + FEATS_ELEMS) + row;
        if (vid >= 0) {
            int izc = vid / (GXX * GYY);
            int rem = vid - izc * (GXX * GYY);
            *co = make_float4((float)b, (float)izc,
                              (float)(rem / GXX), (float)(rem % GXX));
        } else {
            *co = make_float4(-1.f, -1.f, -1.f, -1.f);
        }
    }

    // zeros must land before overwrites to the same tile
    __syncthreads();

    // phase 2: overwrite real points (avg ~1.9 per row)
    if (vid < 0) return;
    int m = cnt < CAP ? cnt : CAP;

    for (int j = sub; j < m; j += 8) {
        int e = (j == sub) ? p0 : (j == sub + 8) ? p1 : __ldg(bk + j);
        // original-order rank: #(entries < e) — bucket line is L1-hot
        int rk = 0;
        for (int q = 0; q < m; q++) rk += (__ldg(bk + q) < e);
        if (rk >= MAXP) continue;
        const float* p = pts + ((size_t)b * NPTS + e) * NC;
        float* fo = out + (size_t)row * ROWF + rk * NC;
        fo[0] = (__ldg(p + 0) - 0.0f)   / 69.12f;
        fo[1] = (__ldg(p + 1) + 39.68f) / 79.36f;
        fo[2] = (__ldg(p + 2) + 3.0f)   / 4.0f;
        fo[3] = __ldg(p + 3);
        fo[4] = __ldg(p + 4);
    }
}

// ---------------- launch ------------------------------------------------------
extern "C" void kernel_launch(void* const* d_in, const int* in_sizes, int n_in,
                              void* d_out, int out_size) {
    const float* pts = (const float*)d_in[0];
    float* out = (float*)d_out;

    k_fill  <<<(FILL_TOTAL + 255) / 256, 256>>>();
    k_points<<<(BB * NPTS + 255) / 256, 256>>>(pts);
    k_scan  <<<BB * NB, 256>>>();
    k_out   <<<NBLK_OUT, 256>>>(pts, out);
}